// round 4
// baseline (speedup 1.0000x reference)
#include <cuda_runtime.h>
#include <cuda_bf16.h>
#include <cstdint>

// Problem dims
#define NUM_NODES 1000000
#define HIDDEN    128
#define OUT_DIM   64
#define FANOUT    16
#define N_SRC0    1048576
#define N_DST0    65536
#define N_DST1    4096

#define TILE_M 32            // dst rows per CTA in fused layer-0 kernel

// ---------------- scratch (static device globals; no allocations) ----------
__device__ float    g_H1[(size_t)N_DST0 * 128];   // layer-0 output (post-ReLU)
__device__ float    g_X1[(size_t)N_DST1 * 256];   // [self | mean] per dst1 row
__device__ uint32_t g_W0T[256 * 128];             // tf32 BITS: [k][n] = cat(W_self0,W_neigh0)^T
__device__ float    g_b0[128];                    // b_self0 + b_neigh0
__device__ float    g_WfT[256 * 64];              // [k][n] = (W_out @ cat(W_self1,W_neigh1))^T
__device__ float    g_bf[64];                     // W_out @ (b_self1+b_neigh1) + b_out

// ---------------- helpers --------------------------------------------------
__device__ __forceinline__ uint32_t f2tf32(float f) {
    uint32_t r; asm("cvt.rna.tf32.f32 %0, %1;" : "=r"(r) : "f"(f)); return r;
}

__device__ __forceinline__ void mma_tf32(float c[4],
                                         uint32_t a0, uint32_t a1, uint32_t a2, uint32_t a3,
                                         uint32_t b0, uint32_t b1) {
    asm volatile(
        "mma.sync.aligned.m16n8k8.row.col.f32.tf32.tf32.f32 "
        "{%0,%1,%2,%3}, {%4,%5,%6,%7}, {%8,%9}, {%0,%1,%2,%3};"
        : "+f"(c[0]), "+f"(c[1]), "+f"(c[2]), "+f"(c[3])
        : "r"(a0), "r"(a1), "r"(a2), "r"(a3), "r"(b0), "r"(b1));
}

__device__ __forceinline__ uint32_t smem_u32(const void* p) {
    uint32_t a;
    asm("{ .reg .u64 t; cvta.to.shared.u64 t, %1; cvt.u32.u64 %0, t; }" : "=r"(a) : "l"(p));
    return a;
}

// ---------------- prep: pack layer-0 weights (store tf32 bits) -------------
__global__ void prep_w0(const float* __restrict__ Ws0, const float* __restrict__ bs0,
                        const float* __restrict__ Wn0, const float* __restrict__ bn0) {
    int idx = blockIdx.x * blockDim.x + threadIdx.x;   // 32768 total
    if (idx < 256 * 128) {
        int k = idx >> 7;
        int n = idx & 127;
        float v = (k < 128) ? Ws0[n * 128 + k] : Wn0[n * 128 + (k - 128)];
        g_W0T[idx] = f2tf32(v);
    }
    if (idx < 128) g_b0[idx] = bs0[idx] + bn0[idx];
}

// ---------------- prep: fuse layer-1 + output projection -------------------
__global__ void prep_wf(const float* __restrict__ Ws1, const float* __restrict__ bs1,
                        const float* __restrict__ Wn1, const float* __restrict__ bn1,
                        const float* __restrict__ Wout, const float* __restrict__ bout) {
    int idx = blockIdx.x * blockDim.x + threadIdx.x;   // 16384 total
    if (idx < 256 * 64) {
        int k = idx >> 6;
        int n = idx & 63;
        float acc = 0.f;
        if (k < 128) {
            #pragma unroll 4
            for (int r = 0; r < 128; r++) acc += Wout[n * 128 + r] * Ws1[r * 128 + k];
        } else {
            int kk = k - 128;
            #pragma unroll 4
            for (int r = 0; r < 128; r++) acc += Wout[n * 128 + r] * Wn1[r * 128 + kk];
        }
        g_WfT[k * 64 + n] = acc;
    }
    if (idx < 64) {
        float acc = bout[idx];
        #pragma unroll 4
        for (int r = 0; r < 128; r++) acc += Wout[idx * 128 + r] * (bs1[r] + bn1[r]);
        g_bf[idx] = acc;
    }
}

// ---------------- fused layer-0: gather + mean + tf32 GEMM + bias + ReLU ---
// TILE_M=32 rows per CTA, 4 CTAs/SM for phase diversity (gather overlaps MMA
// across co-resident CTAs). B chunk 0 prefetched with cp.async under gather.
#define AS_STRIDE 260
#define BS_STRIDE 132
#define SM_AS_WORDS (TILE_M * AS_STRIDE)               // 8320
#define SM_BS_WORDS (32 * BS_STRIDE)                   // 4224
#define SM_IDX_WORDS (TILE_M * FANOUT + TILE_M)        // 544
#define SM_TOTAL_BYTES ((SM_AS_WORDS + SM_BS_WORDS + SM_IDX_WORDS) * 4)

__global__ __launch_bounds__(256, 4) void layer0_fused_kernel(
    const float* __restrict__ emb, const int* __restrict__ input_nodes,
    const int* __restrict__ nbr0) {
    extern __shared__ uint32_t smem[];
    uint32_t (*As)[AS_STRIDE] = (uint32_t (*)[AS_STRIDE])smem;
    uint32_t (*Bs)[BS_STRIDE] = (uint32_t (*)[BS_STRIDE])(smem + SM_AS_WORDS);
    int* s_idx  = (int*)(smem + SM_AS_WORDS + SM_BS_WORDS);          // [32*16]
    int* s_self = s_idx + TILE_M * FANOUT;                           // [32]

    const int tid  = threadIdx.x;
    const int lane = tid & 31;
    const int wid  = tid >> 5;
    const int dst0 = blockIdx.x * TILE_M;

    // ---- prefetch B chunk 0 (tf32 bits, raw copy) under the gather ----
    #pragma unroll
    for (int it = 0; it < 4; it++) {
        int idx = it * 256 + tid;          // 0..1023
        int kk = idx >> 5;
        int n4 = idx & 31;
        uint32_t dst = smem_u32(&Bs[kk][n4 * 4]);
        const uint32_t* src = &g_W0T[(size_t)kk * 128 + n4 * 4];
        asm volatile("cp.async.cg.shared.global [%0], [%1], 16;" :: "r"(dst), "l"(src));
    }
    asm volatile("cp.async.commit_group;");

    // ---- Phase A1: stage composed indices ----
    #pragma unroll
    for (int it = 0; it < (TILE_M * FANOUT) / 256; it++) {           // 2 iters
        int i = it * 256 + tid;
        s_idx[i] = input_nodes[nbr0[(size_t)dst0 * FANOUT + i]];
    }
    if (tid < TILE_M) s_self[tid] = input_nodes[dst0 + tid];
    __syncthreads();

    // ---- Phase A2: feature gather + mean -> tf32 smem A tile ----
    const float4* E = (const float4*)emb;                            // row = 32 float4
    const float inv = 1.0f / (float)FANOUT;
    #pragma unroll
    for (int rr = 0; rr < TILE_M / 8; rr++) {                        // 4 rows per warp
        int r = wid * (TILE_M / 8) + rr;
        float4 s = E[(size_t)s_self[r] * 32 + lane];
        float ax = 0.f, ay = 0.f, az = 0.f, aw = 0.f;
        #pragma unroll
        for (int j = 0; j < FANOUT; j++) {
            int g = s_idx[r * FANOUT + j];
            float4 v = E[(size_t)g * 32 + lane];
            ax += v.x; ay += v.y; az += v.z; aw += v.w;
        }
        uint4 ts; ts.x = f2tf32(s.x); ts.y = f2tf32(s.y); ts.z = f2tf32(s.z); ts.w = f2tf32(s.w);
        *(uint4*)&As[r][lane * 4] = ts;
        uint4 tn; tn.x = f2tf32(ax * inv); tn.y = f2tf32(ay * inv);
        tn.z = f2tf32(az * inv); tn.w = f2tf32(aw * inv);
        *(uint4*)&As[r][128 + lane * 4] = tn;
    }
    asm volatile("cp.async.wait_group 0;");
    __syncthreads();

    // ---- Phase B: GEMM 32x128x256 (tf32 m16n8k8), 8 warps each own 16 cols ----
    const int lm = lane >> 2;          // 0..7
    const int lk = lane & 3;           // 0..3
    const int wn = wid;                // 0..7 -> cols wn*16..wn*16+15

    float acc[2][2][4];
    #pragma unroll
    for (int i = 0; i < 2; i++)
        #pragma unroll
        for (int j = 0; j < 2; j++)
            #pragma unroll
            for (int c = 0; c < 4; c++) acc[i][j][c] = 0.f;

    for (int k0 = 0; k0 < 256; k0 += 32) {
        if (k0) {
            // load next B chunk (tf32 bits, raw uint4 copy, L2-hot)
            #pragma unroll
            for (int it = 0; it < 4; it++) {
                int idx = it * 256 + tid;
                int kk = idx >> 5;
                int n4 = idx & 31;
                *(uint4*)&Bs[kk][n4 * 4] =
                    *(const uint4*)&g_W0T[(size_t)(k0 + kk) * 128 + n4 * 4];
            }
            __syncthreads();
        }

        #pragma unroll
        for (int kk = 0; kk < 4; kk++) {
            const int k8 = kk * 8;
            uint32_t af[2][4], bf[2][2];
            #pragma unroll
            for (int mt = 0; mt < 2; mt++) {
                int mrow = mt * 16 + lm;
                af[mt][0] = As[mrow    ][k0 + k8 + lk];
                af[mt][1] = As[mrow + 8][k0 + k8 + lk];
                af[mt][2] = As[mrow    ][k0 + k8 + lk + 4];
                af[mt][3] = As[mrow + 8][k0 + k8 + lk + 4];
            }
            #pragma unroll
            for (int nt = 0; nt < 2; nt++) {
                int ncol = wn * 16 + nt * 8 + lm;
                bf[nt][0] = Bs[k8 + lk    ][ncol];
                bf[nt][1] = Bs[k8 + lk + 4][ncol];
            }
            #pragma unroll
            for (int mt = 0; mt < 2; mt++)
                #pragma unroll
                for (int nt = 0; nt < 2; nt++)
                    mma_tf32(acc[mt][nt], af[mt][0], af[mt][1], af[mt][2], af[mt][3],
                             bf[nt][0], bf[nt][1]);
        }
        __syncthreads();
    }

    // ---- epilogue: bias + relu -> g_H1 ----
    float2* __restrict__ H2 = (float2*)g_H1;      // row stride = 64 float2
    #pragma unroll
    for (int nt = 0; nt < 2; nt++) {
        int col = wn * 16 + nt * 8 + lk * 2;
        float bv0 = g_b0[col], bv1 = g_b0[col + 1];
        #pragma unroll
        for (int mt = 0; mt < 2; mt++) {
            size_t row0 = (size_t)dst0 + mt * 16 + lm;
            float2 v0 = make_float2(fmaxf(acc[mt][nt][0] + bv0, 0.f),
                                    fmaxf(acc[mt][nt][1] + bv1, 0.f));
            float2 v1 = make_float2(fmaxf(acc[mt][nt][2] + bv0, 0.f),
                                    fmaxf(acc[mt][nt][3] + bv1, 0.f));
            H2[row0 * 64 + (col >> 1)]       = v0;
            H2[(row0 + 8) * 64 + (col >> 1)] = v1;
        }
    }
}

// ---------------- layer-1 gather: build X1 [N_DST1, 256] from g_H1 ---------
__global__ __launch_bounds__(256) void gather1_kernel(const int* __restrict__ nbr1) {
    int warp = (blockIdx.x * blockDim.x + threadIdx.x) >> 5;
    int lane = threadIdx.x & 31;
    if (warp >= N_DST1) return;

    int nj = 0;
    if (lane < FANOUT) nj = nbr1[warp * FANOUT + lane];

    const float4* H = (const float4*)g_H1;                // row stride = 32 float4
    float4 s = H[(size_t)warp * 32 + lane];
    float ax = 0.f, ay = 0.f, az = 0.f, aw = 0.f;
    #pragma unroll
    for (int j = 0; j < FANOUT; j++) {
        int g = __shfl_sync(0xffffffffu, nj, j);
        float4 v = H[(size_t)g * 32 + lane];
        ax += v.x; ay += v.y; az += v.z; aw += v.w;
    }
    const float inv = 1.0f / (float)FANOUT;
    float4* X = (float4*)g_X1;
    X[(size_t)warp * 64 + lane]      = s;
    X[(size_t)warp * 64 + 32 + lane] = make_float4(ax * inv, ay * inv, az * inv, aw * inv);
}

// ---------------- gemm1: out = g_X1 @ g_WfT + g_bf -------------------------
__global__ __launch_bounds__(256) void gemm1_kernel(float* __restrict__ C) {
    __shared__ float Bs[64][65];
    int tid = threadIdx.x;
    int r = blockIdx.x * 4 + (tid >> 6);
    int n = tid & 63;
    float acc = g_bf[n];
    for (int k0 = 0; k0 < 256; k0 += 64) {
        for (int i = tid; i < 64 * 64; i += 256)
            Bs[i >> 6][i & 63] = g_WfT[(size_t)(k0 + (i >> 6)) * 64 + (i & 63)];
        __syncthreads();
        const float* Ar = g_X1 + (size_t)r * 256 + k0;
        #pragma unroll 16
        for (int k = 0; k < 64; k++) acc = fmaf(Ar[k], Bs[k][n], acc);
        __syncthreads();
    }
    C[(size_t)r * 64 + n] = acc;
}

// ---------------- launch ---------------------------------------------------
extern "C" void kernel_launch(void* const* d_in, const int* in_sizes, int n_in,
                              void* d_out, int out_size) {
    const float* emb      = (const float*)d_in[0];
    const float* Ws0      = (const float*)d_in[1];
    const float* bs0      = (const float*)d_in[2];
    const float* Wn0      = (const float*)d_in[3];
    const float* bn0      = (const float*)d_in[4];
    const float* Ws1      = (const float*)d_in[5];
    const float* bs1      = (const float*)d_in[6];
    const float* Wn1      = (const float*)d_in[7];
    const float* bn1      = (const float*)d_in[8];
    const float* Wout     = (const float*)d_in[9];
    const float* bout     = (const float*)d_in[10];
    const int*   in_nodes = (const int*)d_in[11];
    const int*   nbr0     = (const int*)d_in[12];
    const int*   nbr1     = (const int*)d_in[13];
    float* out = (float*)d_out;

    cudaFuncSetAttribute(layer0_fused_kernel,
                         cudaFuncAttributeMaxDynamicSharedMemorySize, SM_TOTAL_BYTES);

    // weight prep (tiny)
    prep_w0<<<128, 256>>>(Ws0, bs0, Wn0, bn0);
    prep_wf<<<64, 256>>>(Ws1, bs1, Wn1, bn1, Wout, bout);

    // layer 0: fused gather + mean + GEMM + bias + ReLU (4 CTAs/SM)
    layer0_fused_kernel<<<N_DST0 / TILE_M, 256, SM_TOTAL_BYTES>>>(emb, in_nodes, nbr0);

    // layer 1 gather, then fused (layer1 + output-projection) GEMM
    gather1_kernel<<<(N_DST1 * 32) / 256, 256>>>(nbr1);
    gemm1_kernel<<<N_DST1 / 4, 256>>>(out);
}

// round 5
// speedup vs baseline: 1.1112x; 1.1112x over previous
#include <cuda_runtime.h>
#include <cuda_bf16.h>
#include <cstdint>

// Problem dims
#define NUM_NODES 1000000
#define HIDDEN    128
#define OUT_DIM   64
#define FANOUT    16
#define N_SRC0    1048576
#define N_DST0    65536
#define N_DST1    4096

#define TILE_M   32
#define NTILES   (N_DST0 / TILE_M)     // 2048
#define GRID0    148                   // persistent CTAs (1 per SM)

// ---------------- scratch (static device globals; no allocations) ----------
__device__ float    g_H1[(size_t)N_DST0 * 128];   // layer-0 output (post-ReLU)
__device__ float    g_X1[(size_t)N_DST1 * 256];   // [self | mean] per dst1 row
__device__ uint32_t g_W0T[256 * 128];             // tf32 BITS: [k][n] = cat(W_self0,W_neigh0)^T
__device__ float    g_b0[128];                    // b_self0 + b_neigh0
__device__ float    g_WfT[256 * 64];              // [k][n] = (W_out @ cat(W_self1,W_neigh1))^T
__device__ float    g_bf[64];                     // W_out @ (b_self1+b_neigh1) + b_out

// ---------------- helpers --------------------------------------------------
__device__ __forceinline__ uint32_t f2tf32(float f) {
    uint32_t r; asm("cvt.rna.tf32.f32 %0, %1;" : "=r"(r) : "f"(f)); return r;
}

__device__ __forceinline__ void mma_tf32(float c[4],
                                         uint32_t a0, uint32_t a1, uint32_t a2, uint32_t a3,
                                         uint32_t b0, uint32_t b1) {
    asm volatile(
        "mma.sync.aligned.m16n8k8.row.col.f32.tf32.tf32.f32 "
        "{%0,%1,%2,%3}, {%4,%5,%6,%7}, {%8,%9}, {%0,%1,%2,%3};"
        : "+f"(c[0]), "+f"(c[1]), "+f"(c[2]), "+f"(c[3])
        : "r"(a0), "r"(a1), "r"(a2), "r"(a3), "r"(b0), "r"(b1));
}

#define MBAR_INIT(addr, cnt) \
    asm volatile("mbarrier.init.shared.b64 [%0], %1;" :: "r"(addr), "r"(cnt) : "memory")
#define MBAR_ARRIVE(addr) \
    asm volatile("mbarrier.arrive.shared.b64 _, [%0];" :: "r"(addr) : "memory")

__device__ __forceinline__ void mbar_wait(uint32_t addr, uint32_t parity) {
    asm volatile(
        "{\n\t"
        ".reg .pred P;\n\t"
        "WL_%=:\n\t"
        "mbarrier.try_wait.parity.acquire.cta.shared::cta.b64 P, [%0], %1, 0x989680;\n\t"
        "@P bra.uni WD_%=;\n\t"
        "bra.uni WL_%=;\n\t"
        "WD_%=:\n\t"
        "}"
        :: "r"(addr), "r"(parity) : "memory");
}

// ---------------- prep: pack layer-0 weights (store tf32 bits) -------------
__global__ void prep_w0(const float* __restrict__ Ws0, const float* __restrict__ bs0,
                        const float* __restrict__ Wn0, const float* __restrict__ bn0) {
    int idx = blockIdx.x * blockDim.x + threadIdx.x;   // 32768 total
    if (idx < 256 * 128) {
        int k = idx >> 7;
        int n = idx & 127;
        float v = (k < 128) ? Ws0[n * 128 + k] : Wn0[n * 128 + (k - 128)];
        g_W0T[idx] = f2tf32(v);
    }
    if (idx < 128) g_b0[idx] = bs0[idx] + bn0[idx];
}

// ---------------- prep: fuse layer-1 + output projection -------------------
__global__ void prep_wf(const float* __restrict__ Ws1, const float* __restrict__ bs1,
                        const float* __restrict__ Wn1, const float* __restrict__ bn1,
                        const float* __restrict__ Wout, const float* __restrict__ bout) {
    int idx = blockIdx.x * blockDim.x + threadIdx.x;   // 16384 total
    if (idx < 256 * 64) {
        int k = idx >> 6;
        int n = idx & 63;
        float acc = 0.f;
        if (k < 128) {
            #pragma unroll 4
            for (int r = 0; r < 128; r++) acc += Wout[n * 128 + r] * Ws1[r * 128 + k];
        } else {
            int kk = k - 128;
            #pragma unroll 4
            for (int r = 0; r < 128; r++) acc += Wout[n * 128 + r] * Wn1[r * 128 + kk];
        }
        g_WfT[k * 64 + n] = acc;
    }
    if (idx < 64) {
        float acc = bout[idx];
        #pragma unroll 4
        for (int r = 0; r < 128; r++) acc += Wout[idx * 128 + r] * (bs1[r] + bn1[r]);
        g_bf[idx] = acc;
    }
}

// ---------------- fused layer-0: warp-specialized producer/consumer --------
// Persistent CTAs. 12 producer warps gather+mean+tf32 into double-buffered
// 32-row A tiles; 4 consumer warps run tf32 MMA against a CTA-resident B and
// write bias+ReLU results. mbarrier full/empty handshake per buffer.
#define AS_STRIDE 260
#define BS_STRIDE 132
#define AS_WORDS  (2 * TILE_M * AS_STRIDE)     // 16640
#define BS_WORDS  (256 * BS_STRIDE)            // 33792
#define MBAR_OFF  (AS_WORDS + BS_WORDS)        // word offset of barriers
#define SM0_BYTES ((MBAR_OFF + 16) * 4)

__global__ __launch_bounds__(512, 1) void layer0_ws_kernel(
    const float* __restrict__ emb, const int* __restrict__ input_nodes,
    const int* __restrict__ nbr0) {
    extern __shared__ uint32_t smem[];
    uint32_t (*Bs)[BS_STRIDE] = (uint32_t (*)[BS_STRIDE])(smem + AS_WORDS);
    uint64_t* mbar = (uint64_t*)(smem + MBAR_OFF);     // [full0, full1, empty0, empty1]

    const int tid  = threadIdx.x;
    const int lane = tid & 31;
    const int wid  = tid >> 5;

    uint32_t mbar_base;
    asm("{ .reg .u64 t; cvta.to.shared.u64 t, %1; cvt.u32.u64 %0, t; }"
        : "=r"(mbar_base) : "l"(mbar));

    if (tid == 0) {
        MBAR_INIT(mbar_base + 0,  384);    // full0  (producer threads arrive)
        MBAR_INIT(mbar_base + 8,  384);    // full1
        MBAR_INIT(mbar_base + 16, 128);    // empty0 (consumer threads arrive)
        MBAR_INIT(mbar_base + 24, 128);    // empty1
    }
    __syncthreads();

    if (wid < 12) {
        // ================= PRODUCER =================
        const float4* E = (const float4*)emb;               // row = 32 float4
        const float inv = 1.0f / (float)FANOUT;
        const int nrows = (wid < 8) ? 3 : 2;                 // rows wid, wid+12, wid+24

        int i = 0;
        for (int t = blockIdx.x; t < NTILES; t += GRID0, i++) {
            const int dst0 = t * TILE_M;
            const int s = i & 1;
            const int u = i >> 1;
            uint32_t (*As)[AS_STRIDE] =
                (uint32_t (*)[AS_STRIDE])(smem + (size_t)s * TILE_M * AS_STRIDE);

            // neighbor + self indices for this warp's rows (issue early)
            int nj[3], sidx[3];
            #pragma unroll
            for (int j = 0; j < 3; j++) {
                if (j < nrows) {
                    int r = wid + j * 12;
                    nj[j] = (lane < FANOUT)
                        ? input_nodes[nbr0[(size_t)(dst0 + r) * FANOUT + lane]] : 0;
                    sidx[j] = input_nodes[dst0 + r];
                } else { nj[j] = 0; sidx[j] = 0; }
            }

            // gather features into registers
            float4 sv[3]; float ax[3], ay[3], az[3], aw[3];
            #pragma unroll
            for (int j = 0; j < 3; j++) {
                if (j >= nrows) continue;
                sv[j] = E[(size_t)sidx[j] * 32 + lane];
                ax[j] = ay[j] = az[j] = aw[j] = 0.f;
                #pragma unroll
                for (int q = 0; q < FANOUT; q++) {
                    int g = __shfl_sync(0xffffffffu, nj[j], q);
                    float4 v = E[(size_t)g * 32 + lane];
                    ax[j] += v.x; ay[j] += v.y; az[j] += v.z; aw[j] += v.w;
                }
            }

            // take the buffer only now (max DRAM overlap)
            if (u > 0) mbar_wait(mbar_base + 16 + s * 8, (u - 1) & 1);

            #pragma unroll
            for (int j = 0; j < 3; j++) {
                if (j >= nrows) continue;
                int r = wid + j * 12;
                uint4 ts; ts.x = f2tf32(sv[j].x); ts.y = f2tf32(sv[j].y);
                ts.z = f2tf32(sv[j].z); ts.w = f2tf32(sv[j].w);
                *(uint4*)&As[r][lane * 4] = ts;
                uint4 tn; tn.x = f2tf32(ax[j] * inv); tn.y = f2tf32(ay[j] * inv);
                tn.z = f2tf32(az[j] * inv); tn.w = f2tf32(aw[j] * inv);
                *(uint4*)&As[r][128 + lane * 4] = tn;
            }
            MBAR_ARRIVE(mbar_base + s * 8);   // full[s]
        }
    } else {
        // ================= CONSUMER =================
        const int cw   = wid - 12;            // 0..3
        const int ctid = cw * 32 + lane;      // 0..127
        const int lm = lane >> 2;
        const int lk = lane & 3;
        const int wn = cw;                    // cols wn*32 .. wn*32+31

        // stage full B once (L2-hot; tf32 bits, raw copy)
        for (int idx = ctid; idx < 256 * 32; idx += 128) {
            int kk = idx >> 5;
            int n4 = idx & 31;
            *(uint4*)&Bs[kk][n4 * 4] = *(const uint4*)&g_W0T[(size_t)kk * 128 + n4 * 4];
        }
        asm volatile("bar.sync 1, 128;" ::: "memory");

        const float b0a = g_b0[wn * 32 + lk * 2];
        const float b0b = g_b0[wn * 32 + lk * 2 + 1];
        const float b1a = g_b0[wn * 32 + 8 + lk * 2];
        const float b1b = g_b0[wn * 32 + 8 + lk * 2 + 1];
        const float b2a = g_b0[wn * 32 + 16 + lk * 2];
        const float b2b = g_b0[wn * 32 + 16 + lk * 2 + 1];
        const float b3a = g_b0[wn * 32 + 24 + lk * 2];
        const float b3b = g_b0[wn * 32 + 24 + lk * 2 + 1];

        int i = 0;
        for (int t = blockIdx.x; t < NTILES; t += GRID0, i++) {
            const int dst0 = t * TILE_M;
            const int s = i & 1;
            const int u = i >> 1;
            uint32_t (*As)[AS_STRIDE] =
                (uint32_t (*)[AS_STRIDE])(smem + (size_t)s * TILE_M * AS_STRIDE);

            mbar_wait(mbar_base + s * 8, u & 1);   // full[s]

            float acc[2][4][4];
            #pragma unroll
            for (int a = 0; a < 2; a++)
                #pragma unroll
                for (int b = 0; b < 4; b++)
                    #pragma unroll
                    for (int c = 0; c < 4; c++) acc[a][b][c] = 0.f;

            #pragma unroll
            for (int k0 = 0; k0 < 256; k0 += 32) {
                #pragma unroll
                for (int kk = 0; kk < 4; kk++) {
                    const int k8 = k0 + kk * 8;
                    uint32_t af[2][4], bf[4][2];
                    #pragma unroll
                    for (int mt = 0; mt < 2; mt++) {
                        int mrow = mt * 16 + lm;
                        af[mt][0] = As[mrow    ][k8 + lk];
                        af[mt][1] = As[mrow + 8][k8 + lk];
                        af[mt][2] = As[mrow    ][k8 + lk + 4];
                        af[mt][3] = As[mrow + 8][k8 + lk + 4];
                    }
                    #pragma unroll
                    for (int nt = 0; nt < 4; nt++) {
                        int ncol = wn * 32 + nt * 8 + lm;
                        bf[nt][0] = Bs[k8 - k0 + (k0 + lk)][0];  // placeholder (replaced below)
                        bf[nt][0] = Bs[k8 + lk    ][ncol];
                        bf[nt][1] = Bs[k8 + lk + 4][ncol];
                    }
                    #pragma unroll
                    for (int mt = 0; mt < 2; mt++)
                        #pragma unroll
                        for (int nt = 0; nt < 4; nt++)
                            mma_tf32(acc[mt][nt], af[mt][0], af[mt][1], af[mt][2], af[mt][3],
                                     bf[nt][0], bf[nt][1]);
                }
            }

            MBAR_ARRIVE(mbar_base + 16 + s * 8);   // empty[s] (A fully consumed)

            // epilogue: bias + relu -> g_H1
            float2* __restrict__ H2 = (float2*)g_H1;     // row stride = 64 float2
            const float bias[4][2] = {{b0a,b0b},{b1a,b1b},{b2a,b2b},{b3a,b3b}};
            #pragma unroll
            for (int nt = 0; nt < 4; nt++) {
                int col = wn * 32 + nt * 8 + lk * 2;
                #pragma unroll
                for (int mt = 0; mt < 2; mt++) {
                    size_t row0 = (size_t)dst0 + mt * 16 + lm;
                    float2 v0 = make_float2(fmaxf(acc[mt][nt][0] + bias[nt][0], 0.f),
                                            fmaxf(acc[mt][nt][1] + bias[nt][1], 0.f));
                    float2 v1 = make_float2(fmaxf(acc[mt][nt][2] + bias[nt][0], 0.f),
                                            fmaxf(acc[mt][nt][3] + bias[nt][1], 0.f));
                    H2[row0 * 64 + (col >> 1)]       = v0;
                    H2[(row0 + 8) * 64 + (col >> 1)] = v1;
                }
            }
        }
    }
}

// ---------------- layer-1 gather: build X1 [N_DST1, 256] from g_H1 ---------
__global__ __launch_bounds__(256) void gather1_kernel(const int* __restrict__ nbr1) {
    int warp = (blockIdx.x * blockDim.x + threadIdx.x) >> 5;
    int lane = threadIdx.x & 31;
    if (warp >= N_DST1) return;

    int nj = 0;
    if (lane < FANOUT) nj = nbr1[warp * FANOUT + lane];

    const float4* H = (const float4*)g_H1;                // row stride = 32 float4
    float4 s = H[(size_t)warp * 32 + lane];
    float ax = 0.f, ay = 0.f, az = 0.f, aw = 0.f;
    #pragma unroll
    for (int j = 0; j < FANOUT; j++) {
        int g = __shfl_sync(0xffffffffu, nj, j);
        float4 v = H[(size_t)g * 32 + lane];
        ax += v.x; ay += v.y; az += v.z; aw += v.w;
    }
    const float inv = 1.0f / (float)FANOUT;
    float4* X = (float4*)g_X1;
    X[(size_t)warp * 64 + lane]      = s;
    X[(size_t)warp * 64 + 32 + lane] = make_float4(ax * inv, ay * inv, az * inv, aw * inv);
}

// ---------------- gemm1: out = g_X1 @ g_WfT + g_bf -------------------------
__global__ __launch_bounds__(256) void gemm1_kernel(float* __restrict__ C) {
    __shared__ float Bs[64][65];
    int tid = threadIdx.x;
    int r = blockIdx.x * 4 + (tid >> 6);
    int n = tid & 63;
    float acc = g_bf[n];
    for (int k0 = 0; k0 < 256; k0 += 64) {
        for (int i = tid; i < 64 * 64; i += 256)
            Bs[i >> 6][i & 63] = g_WfT[(size_t)(k0 + (i >> 6)) * 64 + (i & 63)];
        __syncthreads();
        const float* Ar = g_X1 + (size_t)r * 256 + k0;
        #pragma unroll 16
        for (int k = 0; k < 64; k++) acc = fmaf(Ar[k], Bs[k][n], acc);
        __syncthreads();
    }
    C[(size_t)r * 64 + n] = acc;
}

// ---------------- launch ---------------------------------------------------
extern "C" void kernel_launch(void* const* d_in, const int* in_sizes, int n_in,
                              void* d_out, int out_size) {
    const float* emb      = (const float*)d_in[0];
    const float* Ws0      = (const float*)d_in[1];
    const float* bs0      = (const float*)d_in[2];
    const float* Wn0      = (const float*)d_in[3];
    const float* bn0      = (const float*)d_in[4];
    const float* Ws1      = (const float*)d_in[5];
    const float* bs1      = (const float*)d_in[6];
    const float* Wn1      = (const float*)d_in[7];
    const float* bn1      = (const float*)d_in[8];
    const float* Wout     = (const float*)d_in[9];
    const float* bout     = (const float*)d_in[10];
    const int*   in_nodes = (const int*)d_in[11];
    const int*   nbr0     = (const int*)d_in[12];
    const int*   nbr1     = (const int*)d_in[13];
    float* out = (float*)d_out;

    cudaFuncSetAttribute(layer0_ws_kernel,
                         cudaFuncAttributeMaxDynamicSharedMemorySize, SM0_BYTES);

    // weight prep (tiny)
    prep_w0<<<128, 256>>>(Ws0, bs0, Wn0, bn0);
    prep_wf<<<64, 256>>>(Ws1, bs1, Wn1, bn1, Wout, bout);

    // layer 0: persistent warp-specialized gather + GEMM
    layer0_ws_kernel<<<GRID0, 512, SM0_BYTES>>>(emb, in_nodes, nbr0);

    // layer 1 gather, then fused (layer1 + output-projection) GEMM
    gather1_kernel<<<(N_DST1 * 32) / 256, 256>>>(nbr1);
    gemm1_kernel<<<N_DST1 / 4, 256>>>(out);
}